// round 16
// baseline (speedup 1.0000x reference)
#include <cuda_runtime.h>
#include <cstdint>

#define NN   8192
#define DIN  128
#define BM   64
#define KC   64
#define NCH  (NN / KC)                       // 128
#define THREADS 512
#define GRID (NN / BM)

#define TSTR 68                              // A-tile row stride (floats); 68%32=4 -> conflict-free frags
#define XSTR 136                             // x tile row stride (floats)
#define ARR_FLOATS (BM * TSTR)               // 4352 (one A-tile)
#define XTILE (KC * XSTR)                    // 8704
#define AT_OFF (4 * XTILE)                   // 34816 (4 x slots first)
#define MAIN_FLOATS (AT_OFF + 2 * ARR_FLOATS)   // 43520 (174080 B)

#define HSTRIDE 132
#define WSTRIDE 130
#define EPI_FLOATS (BM * HSTRIDE + DIN * WSTRIDE)   // 25088 (100352 B)

#define SMEM_FLOATS (MAIN_FLOATS > EPI_FLOATS ? MAIN_FLOATS : EPI_FLOATS)
#define SMEM_BYTES (SMEM_FLOATS * 4)         // 174080

typedef unsigned long long ull;

// ---------------- helpers ----------------
__device__ __forceinline__ uint32_t smem_u32(const void* p) {
    uint32_t r;
    asm("{ .reg .u64 t; cvta.to.shared.u64 t, %1; cvt.u32.u64 %0, t; }" : "=r"(r) : "l"(p));
    return r;
}
__device__ __forceinline__ void cpasync16(uint32_t dst, const void* src) {
    asm volatile("cp.async.cg.shared.global [%0], [%1], 16;" :: "r"(dst), "l"(src));
}
#define CP_COMMIT() asm volatile("cp.async.commit_group;" ::: "memory")
#define CP_WAIT(n)  asm volatile("cp.async.wait_group %0;" :: "n"(n) : "memory")

__device__ __forceinline__ uint32_t cvt_tf32(float v) {
    uint32_t r; asm("cvt.rna.tf32.f32 %0, %1;" : "=r"(r) : "f"(v)); return r;
}
__device__ __forceinline__ void mma_tf32(float* d, const uint32_t* a, uint32_t b0, uint32_t b1) {
    asm volatile(
        "mma.sync.aligned.m16n8k8.row.col.f32.tf32.tf32.f32 "
        "{%0,%1,%2,%3}, {%4,%5,%6,%7}, {%8,%9}, {%0,%1,%2,%3};"
        : "+f"(d[0]), "+f"(d[1]), "+f"(d[2]), "+f"(d[3])
        : "r"(a[0]), "r"(a[1]), "r"(a[2]), "r"(a[3]), "r"(b0), "r"(b1));
}
__device__ __forceinline__ void ffma2(ull& acc, ull q, ull x) {
    asm volatile("fma.rn.f32x2 %0, %1, %2, %0;" : "+l"(acc) : "l"(q), "l"(x));
}
__device__ __forceinline__ ull rep2(float v) {
    ull r; asm("mov.b64 %0, {%1, %1};" : "=l"(r) : "f"(v)); return r;
}
__device__ __forceinline__ ull pack2(float lo, float hi) {
    ull r; asm("mov.b64 %0, {%1, %2};" : "=l"(r) : "f"(lo), "f"(hi)); return r;
}
__device__ __forceinline__ float2 unp2(ull v) {
    float2 r; asm("mov.b64 {%0, %1}, %2;" : "=f"(r.x), "=f"(r.y) : "l"(v)); return r;
}

__global__ void __launch_bounds__(THREADS, 1)
ggd_kernel(const float* __restrict__ theta,
           const float* __restrict__ T,      // [4][8192][8192]
           const float* __restrict__ x,      // [8192][128]
           const float* __restrict__ a,      // [8192][8192]
           const float* __restrict__ alpha,  // [128]
           const float* __restrict__ W,      // [128][128]
           const float* __restrict__ bias,   // [128]
           float* __restrict__ out)          // [8192][128]
{
    extern __shared__ float smf[];
    const uint32_t sb = smem_u32(smf);
    const int tid  = threadIdx.x;
    const int lane = tid & 31;
    const int wid  = tid >> 5;          // 0..15
    const int wm   = wid & 3;           // 16-row m-tile
    const int wn   = wid >> 2;          // 32-col n-group
    const int i0   = blockIdx.x * BM;

    const float th0 = theta[0], th1 = theta[1], th2 = theta[2], th3 = theta[3];

    // ---- T/a register-path load: warp w owns rows 4w..4w+3; cols lane, lane+32 ----
    const size_t SLICE = (size_t)NN * NN;
    const float* pTA[5];
    #pragma unroll
    for (int k = 0; k < 4; ++k)
        pTA[k] = T + k * SLICE + (size_t)(i0 + 4 * wid) * NN + lane;
    pTA[4] = a + (size_t)(i0 + 4 * wid) * NN + lane;

    float buf[40];                       // [arr][row][col2] prefetch buffer
    auto LDGT = [&](int ch) {
        const int j0 = ch * KC;
        #pragma unroll
        for (int arr = 0; arr < 5; ++arr)
            #pragma unroll
            for (int r = 0; r < 4; ++r)
                #pragma unroll
                for (int c = 0; c < 2; ++c)
                    buf[arr * 8 + r * 2 + c] =
                        __ldcs(pTA[arr] + (size_t)r * NN + j0 + 32 * c);
    };

    // q-build from registers -> A-tile (17KB STS, conflict-free)
    auto QBUILD = [&](int ch) {
        float* at = smf + AT_OFF + (ch & 1) * ARR_FLOATS;
        #pragma unroll
        for (int r = 0; r < 4; ++r)
            #pragma unroll
            for (int c = 0; c < 2; ++c) {
                const int ix = r * 2 + c;
                const float q = buf[32 + ix] *
                    (th0 * buf[ix] + th1 * buf[8 + ix] + th2 * buf[16 + ix] + th3 * buf[24 + ix]);
                uint32_t qi = cvt_tf32(q);
                *(uint32_t*)(void*)(at + (4 * wid + r) * TSTR + lane + 32 * c) = qi;
            }
    };

    // ---- x staging via cp.async: 64 rows x 128 cols per chunk ----
    const int xcol = tid & 31;          // 16B granule within 512B x row
    const int xrow = tid >> 5;          // 0..15 (+16*rr)
    const float* gx = x + (size_t)xrow * DIN + xcol * 4;
    auto LOADX = [&](int ch) {
        const int j0 = ch * KC;
        const uint32_t xbase = sb + (uint32_t)((ch & 3) * XTILE) * 4u;
        #pragma unroll
        for (int rr = 0; rr < 4; ++rr) {
            const uint32_t dst = xbase +
                (uint32_t)((xrow + 16 * rr) * XSTR + xcol * 4) * 4u;
            cpasync16(dst, gx + (size_t)(j0 + 16 * rr) * DIN);
        }
        CP_COMMIT();
    };

    // ---- MMA fragment bases ----
    const int abase = (16 * wm + (lane >> 2)) * TSTR + (lane & 3);
    const int bbase = (lane & 3) * XSTR + 32 * wn + (lane >> 2);

    float acc[4][4];
    #pragma unroll
    for (int nt = 0; nt < 4; ++nt)
        #pragma unroll
        for (int c = 0; c < 4; ++c) acc[nt][c] = 0.0f;

    // prologue
    LOADX(0);
    LOADX(1);
    LDGT(0);
    QBUILD(0);                 // one-time exposed LDG latency
    LDGT(1);

    for (int ch = 0; ch < NCH; ++ch) {
        if (ch + 2 < NCH) { LOADX(ch + 2); CP_WAIT(1); }
        else              { CP_WAIT(0); }
        __syncthreads();       // A-tile(ch) + x(ch) visible; prior slot readers done
        {
            const uint32_t* At = (const uint32_t*)(smf + AT_OFF + (ch & 1) * ARR_FLOATS);
            const uint32_t* Bs = (const uint32_t*)(smf + (ch & 3) * XTILE);
            #pragma unroll
            for (int ks = 0; ks < 8; ++ks) {
                uint32_t af[4];
                const int ab = abase + 8 * ks;
                af[0] = At[ab];
                af[1] = At[ab + 8 * TSTR];
                af[2] = At[ab + 4];
                af[3] = At[ab + 8 * TSTR + 4];
                #pragma unroll
                for (int nt = 0; nt < 4; ++nt) {
                    const int bb = bbase + 8 * ks * XSTR + 8 * nt;
                    mma_tf32(acc[nt], af, Bs[bb], Bs[bb + 4 * XSTR]);
                }
            }
        }
        if (ch + 1 < NCH) QBUILD(ch + 1);    // consumes buf(ch+1), writes other A-buf
        if (ch + 2 < NCH) LDGT(ch + 2);      // refill regs; ~1 chunk of latency cover
    }
    __syncthreads();           // all MMA/LDS done before smem reuse

    // ---------------- epilogue: PReLU -> hs, then @ W^T + b (fp32) ----------------
    float* hs = smf;                     // [BM][HSTRIDE]    8448 floats
    float* wt = smf + BM * HSTRIDE;      // [DIN][WSTRIDE]  16640 floats (25088 total, fits)

    {
        const int r0 = 16 * wm + (lane >> 2);
        #pragma unroll
        for (int nt = 0; nt < 4; ++nt) {
            const int col = 32 * wn + 8 * nt + 2 * (lane & 3);
            const float a0 = __ldg(alpha + col), a1 = __ldg(alpha + col + 1);
            float2 h0, h1;
            h0.x = acc[nt][0] > 0.0f ? acc[nt][0] : a0 * acc[nt][0];
            h0.y = acc[nt][1] > 0.0f ? acc[nt][1] : a1 * acc[nt][1];
            h1.x = acc[nt][2] > 0.0f ? acc[nt][2] : a0 * acc[nt][2];
            h1.y = acc[nt][3] > 0.0f ? acc[nt][3] : a1 * acc[nt][3];
            *(float2*)(hs + r0 * HSTRIDE + col)       = h0;
            *(float2*)(hs + (r0 + 8) * HSTRIDE + col) = h1;
        }
    }
    for (int idx = tid; idx < DIN * DIN; idx += THREADS) {
        const int din = idx >> 7, dof = idx & 127;
        wt[din * WSTRIDE + dof] = __ldg(W + dof * DIN + din);
    }
    __syncthreads();

    const int ti = tid >> 4;             // 0..31 -> 2 rows each
    const int td = tid & 15;
    ull oacc[2][4];
    #pragma unroll
    for (int c2 = 0; c2 < 4; ++c2) {
        const int d0 = 2 * (td + 16 * c2);
        const float2 bb = *(const float2*)(bias + d0);
        const ull bv = pack2(bb.x, bb.y);
        #pragma unroll
        for (int r = 0; r < 2; ++r) oacc[r][c2] = bv;
    }
    #pragma unroll 4
    for (int din = 0; din < DIN; ++din) {
        ull wv[4];
        #pragma unroll
        for (int c2 = 0; c2 < 4; ++c2)
            wv[c2] = *(const ull*)(wt + din * WSTRIDE + 2 * (td + 16 * c2));
        #pragma unroll
        for (int r = 0; r < 2; ++r) {
            const ull h2 = rep2(hs[(ti * 2 + r) * HSTRIDE + din]);
            #pragma unroll
            for (int c2 = 0; c2 < 4; ++c2) ffma2(oacc[r][c2], h2, wv[c2]);
        }
    }
    #pragma unroll
    for (int r = 0; r < 2; ++r) {
        float* orow = out + (size_t)(i0 + ti * 2 + r) * DIN;
        #pragma unroll
        for (int c2 = 0; c2 < 4; ++c2) {
            const float2 o = unp2(oacc[r][c2]);
            *(float2*)(orow + 2 * (td + 16 * c2)) = o;
        }
    }
}

extern "C" void kernel_launch(void* const* d_in, const int* in_sizes, int n_in,
                              void* d_out, int out_size) {
    const float* theta = (const float*)d_in[0];
    const float* T     = (const float*)d_in[1];
    const float* x     = (const float*)d_in[2];
    const float* a     = (const float*)d_in[3];
    const float* alpha = (const float*)d_in[4];
    const float* W     = (const float*)d_in[5];
    const float* b     = (const float*)d_in[6];
    float* out = (float*)d_out;

    cudaFuncSetAttribute(ggd_kernel, cudaFuncAttributeMaxDynamicSharedMemorySize, SMEM_BYTES);
    ggd_kernel<<<GRID, THREADS, SMEM_BYTES>>>(theta, T, x, a, alpha, W, b, out);
}